// round 16
// baseline (speedup 1.0000x reference)
#include <cuda_runtime.h>
#include <cuda_fp16.h>
#include <math.h>

#define N_NODES 4096
#define F_IN 512
#define H_HEADS 8
#define C_OUT 128
#define HC (H_HEADS * C_OUT)   // 1024
#define ALPHA 0.2f
#define MAX_DEG 256   // deg ~ Binom(4096,0.01)+1 = 42±6.4; 256 is a >30-sigma guard
#define AGG_CTAS 1184 // 8 CTAs/SM x 148 SMs (persistent work-stealing grid)

// Scratch (allocation-free rule: __device__ globals)
__device__ __half g_feats_h[N_NODES * HC];    // 8 MB (L2-resident)
__device__ float  g_sself[H_HEADS * N_NODES];
__device__ float  g_sneigh[H_HEADS * N_NODES];
__device__ float  g_Xr[N_NODES * F_IN];          // rna-tf32-rounded X (8 MB)
__device__ float  g_Wr[H_HEADS * F_IN * C_OUT];  // rna-tf32-rounded W (2 MB)
__device__ unsigned g_ticket;                    // agg work-stealing counter

// ---------------------------------------------------------------------------
__device__ __forceinline__ float tf32_rna(float x) {
    unsigned u;
    asm("cvt.rna.tf32.f32 %0, %1;" : "=r"(u) : "f"(x));
    return __uint_as_float(u);
}

__device__ __forceinline__ void mma_tf32(float* c, const unsigned* a, const unsigned* b) {
    asm volatile(
        "mma.sync.aligned.m16n8k8.row.col.f32.tf32.tf32.f32 "
        "{%0,%1,%2,%3}, {%4,%5,%6,%7}, {%8,%9}, {%0,%1,%2,%3};"
        : "+f"(c[0]), "+f"(c[1]), "+f"(c[2]), "+f"(c[3])
        : "r"(a[0]), "r"(a[1]), "r"(a[2]), "r"(a[3]), "r"(b[0]), "r"(b[1]));
}

__device__ __forceinline__ void cp_async16(unsigned smem_addr, const void* gptr) {
    asm volatile("cp.async.cg.shared.global [%0], [%1], 16;"
                 :: "r"(smem_addr), "l"(gptr));
}

// ---------------------------------------------------------------------------
// Prepass: rna-round X and W to tf32 (measured-best config: 2560 blocks,
// one float4 per thread). Also resets the agg work-stealing ticket.
// Fires PDL launch_dependents at entry so gemm's launch overlaps us.
// ---------------------------------------------------------------------------
__global__ __launch_bounds__(256) void prep_kernel(const float* __restrict__ X,
                                                   const float* __restrict__ W) {
    asm volatile("griddepcontrol.launch_dependents;");
    if (blockIdx.x == 0 && threadIdx.x == 0) g_ticket = 0;

    const int idx = blockIdx.x * 256 + threadIdx.x;   // float4 index
    const int nX = N_NODES * F_IN / 4;                // 524288
    const int nW = H_HEADS * F_IN * C_OUT / 4;        // 131072
    if (idx < nX) {
        float4 v = reinterpret_cast<const float4*>(X)[idx];
        v.x = tf32_rna(v.x); v.y = tf32_rna(v.y);
        v.z = tf32_rna(v.z); v.w = tf32_rna(v.w);
        reinterpret_cast<float4*>(g_Xr)[idx] = v;
    } else if (idx < nX + nW) {
        const int j = idx - nX;
        float4 v = reinterpret_cast<const float4*>(W)[j];
        v.x = tf32_rna(v.x); v.y = tf32_rna(v.y);
        v.z = tf32_rna(v.z); v.w = tf32_rna(v.w);
        reinterpret_cast<float4*>(g_Wr)[j] = v;
    }
}

// ---------------------------------------------------------------------------
// TF32 tensor-core GEMM + fused score epilogue.  (R14 config, unchanged.)
// PDL: waits for prep before reading g_Xr/g_Wr; releases agg at entry.
// ---------------------------------------------------------------------------
#define AS_STRIDE 36   // bank = (4r + c) % 32 -> conflict-free frag loads
#define BS_STRIDE 136  // bank = (8k + n) % 32 -> conflict-free frag loads
#define AS_SIZE (128 * AS_STRIDE)   // floats per buffer
#define BS_SIZE (32 * BS_STRIDE)
#define GEMM_DYN_SMEM ((2 * AS_SIZE + 2 * BS_SIZE) * 4)   // 71680 B

__global__ __launch_bounds__(256, 2) void gemm_kernel(const float* __restrict__ a_self,
                                                      const float* __restrict__ a_neigh) {
    asm volatile("griddepcontrol.launch_dependents;");

    extern __shared__ float dyn[];
    float* Asm = dyn;                  // [2][128][AS_STRIDE]
    float* Bsm = dyn + 2 * AS_SIZE;    // [2][32][BS_STRIDE]
    __shared__ float sredS[4][128];
    __shared__ float sredN[4][128];

    const int h  = blockIdx.x;
    const int m0 = blockIdx.y * 128;
    const float* Xr = g_Xr;
    const float* Wh = g_Wr + (size_t)h * F_IN * C_OUT;

    const int t    = threadIdx.x;
    const int lane = t & 31;
    const int w    = t >> 5;
    const int warp_m = (w & 1) * 64;
    const int warp_n = (w >> 1) * 32;

    float acc[4][4][4];
#pragma unroll
    for (int mt = 0; mt < 4; mt++)
#pragma unroll
        for (int nt = 0; nt < 4; nt++)
#pragma unroll
            for (int q = 0; q < 4; q++) acc[mt][nt][q] = 0.0f;

    const int a_row  = t >> 3;        // 0..31 (+32p)
    const int a_col4 = (t & 7) * 4;
    const int b_row  = t >> 5;        // 0..7 (+8p)
    const int b_col4 = (t & 31) * 4;

    const unsigned sA = (unsigned)__cvta_generic_to_shared(Asm);
    const unsigned sB = (unsigned)__cvta_generic_to_shared(Bsm);

    auto issue_chunk = [&](int chunk) {
        const int buf = chunk & 1;
        const int k0  = chunk * 32;
#pragma unroll
        for (int p = 0; p < 4; p++) {
            cp_async16(sA + (unsigned)(buf * AS_SIZE +
                             (a_row + 32 * p) * AS_STRIDE + a_col4) * 4u,
                       Xr + (size_t)(m0 + a_row + 32 * p) * F_IN + k0 + a_col4);
            cp_async16(sB + (unsigned)(buf * BS_SIZE +
                             (b_row + 8 * p) * BS_STRIDE + b_col4) * 4u,
                       Wh + (size_t)(k0 + b_row + 8 * p) * C_OUT + b_col4);
        }
        asm volatile("cp.async.commit_group;" ::: "memory");
    };

    // Wait for prep's stores (PDL join; no-op on plain launch).
    asm volatile("griddepcontrol.wait;" ::: "memory");

    issue_chunk(0);

    for (int chunk = 0; chunk < F_IN / 32; chunk++) {
        if (chunk + 1 < F_IN / 32) {
            issue_chunk(chunk + 1);
            asm volatile("cp.async.wait_group 1;" ::: "memory");
        } else {
            asm volatile("cp.async.wait_group 0;" ::: "memory");
        }
        __syncthreads();

        const unsigned* Au = reinterpret_cast<const unsigned*>(Asm + (chunk & 1) * AS_SIZE);
        const unsigned* Bu = reinterpret_cast<const unsigned*>(Bsm + (chunk & 1) * BS_SIZE);

#pragma unroll
        for (int ks = 0; ks < 32; ks += 8) {
            unsigned afr[4][4], bfr[4][2];
            const int r0 = warp_m + (lane >> 2);
            const int cA = ks + (lane & 3);
#pragma unroll
            for (int mt = 0; mt < 4; mt++) {
                const int r = r0 + mt * 16;
                afr[mt][0] = Au[r * AS_STRIDE + cA];
                afr[mt][1] = Au[(r + 8) * AS_STRIDE + cA];
                afr[mt][2] = Au[r * AS_STRIDE + cA + 4];
                afr[mt][3] = Au[(r + 8) * AS_STRIDE + cA + 4];
            }
            const int rB = ks + (lane & 3);
            const int nB = warp_n + (lane >> 2);
#pragma unroll
            for (int nt = 0; nt < 4; nt++) {
                bfr[nt][0] = Bu[rB * BS_STRIDE + nB + nt * 8];
                bfr[nt][1] = Bu[(rB + 4) * BS_STRIDE + nB + nt * 8];
            }
#pragma unroll
            for (int mt = 0; mt < 4; mt++)
#pragma unroll
                for (int nt = 0; nt < 4; nt++)
                    mma_tf32(acc[mt][nt], afr[mt], bfr[nt]);
        }
        __syncthreads();
    }

    // ---- Epilogue: fp16 feats store + fused score reduction ----
    const int rloc  = warp_m + (lane >> 2);
    const int cloc  = warp_n + (lane & 3) * 2;
    const int cbase = h * C_OUT + cloc;

    float asf[4][2], anf[4][2];
#pragma unroll
    for (int nt = 0; nt < 4; nt++) {
        float2 s2 = *reinterpret_cast<const float2*>(a_self  + h * C_OUT + cloc + nt * 8);
        float2 n2 = *reinterpret_cast<const float2*>(a_neigh + h * C_OUT + cloc + nt * 8);
        asf[nt][0] = s2.x; asf[nt][1] = s2.y;
        anf[nt][0] = n2.x; anf[nt][1] = n2.y;
    }

#pragma unroll
    for (int mt = 0; mt < 4; mt++) {
#pragma unroll
        for (int p = 0; p < 2; p++) {
            const int r = m0 + rloc + mt * 16 + p * 8;
            float ssp = 0.0f, snp = 0.0f;
#pragma unroll
            for (int nt = 0; nt < 4; nt++) {
                const float v0 = acc[mt][nt][2 * p];
                const float v1 = acc[mt][nt][2 * p + 1];
                ssp = fmaf(v0, asf[nt][0], ssp);
                ssp = fmaf(v1, asf[nt][1], ssp);
                snp = fmaf(v0, anf[nt][0], snp);
                snp = fmaf(v1, anf[nt][1], snp);
                __half2 hv = __floats2half2_rn(v0, v1);
                *reinterpret_cast<__half2*>(g_feats_h + (size_t)r * HC + cbase + nt * 8) = hv;
            }
            ssp += __shfl_xor_sync(0xffffffffu, ssp, 1);
            ssp += __shfl_xor_sync(0xffffffffu, ssp, 2);
            snp += __shfl_xor_sync(0xffffffffu, snp, 1);
            snp += __shfl_xor_sync(0xffffffffu, snp, 2);
            if ((lane & 3) == 0) {
                const int rl = rloc + mt * 16 + p * 8;
                sredS[w >> 1][rl] = ssp;
                sredN[w >> 1][rl] = snp;
            }
        }
    }
    __syncthreads();
    if (t < 128) {
        float ss = sredS[0][t] + sredS[1][t] + sredS[2][t] + sredS[3][t];
        float sn = sredN[0][t] + sredN[1][t] + sredN[2][t] + sredN[3][t];
        g_sself[h * N_NODES + m0 + t]  = ss;
        g_sneigh[h * N_NODES + m0 + t] = sn;
    }
}

// ---------------------------------------------------------------------------
// Aggregation: PERSISTENT work-stealing CTAs (deterministic: each row's
// result is self-contained and order-independent). Per row: compaction
// (reads only A — overlaps gemm tail under PDL), griddepcontrol.wait,
// exp+Z pass, sync-free fp16 gather.
// ---------------------------------------------------------------------------
__global__ __launch_bounds__(256) void agg_kernel(const float* __restrict__ A,
                                                  const float* __restrict__ bias,
                                                  float* __restrict__ out) {
    __shared__ int   nbr[MAX_DEG];             // 1 KB
    __shared__ float exps_t[H_HEADS][MAX_DEG]; // 8 KB (unnormalized e)
    __shared__ int   warp_cnt[8];
    __shared__ float sInvZ[H_HEADS];
    __shared__ float red[128][8];              // 4 KB
    __shared__ unsigned s_row;

    const int t    = threadIdx.x;
    const int lane = t & 31;
    const int w    = t >> 5;

    for (;;) {
        if (t == 0) s_row = atomicAdd(&g_ticket, 1u);
        __syncthreads();   // also fences smem reuse across iterations
        const unsigned i = s_row;
        if (i >= N_NODES) return;

        const float* Arow = A + (size_t)i * N_NODES;

        // ---- 1) compaction: count first, then write at final position ----
        float4 v4[4];
        unsigned bal[16];
        {
            const float* Aseg = Arow + (w << 9);  // warp owns 512 cols
#pragma unroll
            for (int b = 0; b < 4; b++)
                v4[b] = reinterpret_cast<const float4*>(Aseg)[(b << 5) + lane];
            int wcnt = 0;
            const float* vf = reinterpret_cast<const float*>(v4);
#pragma unroll
            for (int s = 0; s < 16; s++) {
                const bool p = (vf[s] != 0.0f);
                bal[s] = __ballot_sync(0xffffffffu, p);
                wcnt += __popc(bal[s]);
            }
            if (lane == 0) warp_cnt[w] = wcnt;
        }
        __syncthreads();

        int pref[9];
        pref[0] = 0;
#pragma unroll
        for (int ww = 0; ww < 8; ww++) pref[ww + 1] = pref[ww] + warp_cnt[ww];
        const int deg  = min(pref[8], MAX_DEG);          // >= 1 (self loop)
        const int degp = min((deg + 3) & ~3, MAX_DEG);   // padded to mult of 4

        {
            const unsigned lmask = (1u << lane) - 1u;
            int running = pref[w];
            const float* vf = reinterpret_cast<const float*>(v4);
#pragma unroll
            for (int s = 0; s < 16; s++) {
                const bool p = (vf[s] != 0.0f);
                if (p) {
                    const int pos = running + __popc(bal[s] & lmask);
                    const int col = (w << 9) + ((s >> 2) << 7) + (lane << 2) + (s & 3);
                    if (pos < MAX_DEG) nbr[pos] = col;
                }
                running += __popc(bal[s]);
            }
            if (t < 4 && deg + t < degp) nbr[deg + t] = 0;
        }
        __syncthreads();

        // PDL join: gemm's stores visible after this (no-op once complete).
        asm volatile("griddepcontrol.wait;" ::: "memory");

        // ---- 2) exp pass + Z; warp w handles head w (no max shift) ----
        {
            const float ss = g_sself[(w << 12) + i];
            const float* snh = g_sneigh + (w << 12);
            float Z = 0.0f;
            for (int k = lane; k < degp; k += 32) {
                float e = 0.0f;
                if (k < deg) {
                    float x = ss + snh[nbr[k]];
                    x = (x > 0.0f) ? x : ALPHA * x;
                    e = __expf(x);
                }
                exps_t[w][k] = e;
                Z += e;
            }
#pragma unroll
            for (int o = 16; o > 0; o >>= 1)
                Z += __shfl_xor_sync(0xffffffffu, Z, o);
            if (lane == 0) sInvZ[w] = 1.0f / Z;
        }
        __syncthreads();

        // ---- 3) sync-free gather: adjacent pair per thread, LDS.64 coefs ----
        const int hh_t    = (t & 127) >> 4;
        const unsigned colbase = (unsigned)((t & 127) << 3);
        const int ksel    = t >> 7;
        float acc[8];
#pragma unroll
        for (int q = 0; q < 8; q++) acc[q] = 0.0f;

        for (int m = 0; m < degp; m += 4) {
            const int k1 = m + (ksel << 1);
            const int j1 = nbr[k1];
            const int j2 = nbr[k1 + 1];
            const uint4 v1 = *reinterpret_cast<const uint4*>(
                g_feats_h + (((unsigned)j1) << 10) + colbase);
            const uint4 v2 = *reinterpret_cast<const uint4*>(
                g_feats_h + (((unsigned)j2) << 10) + colbase);
            const float2 c = *reinterpret_cast<const float2*>(&exps_t[hh_t][k1]);
            {
                const float2 f0 = __half22float2(*reinterpret_cast<const __half2*>(&v1.x));
                const float2 f1 = __half22float2(*reinterpret_cast<const __half2*>(&v1.y));
                const float2 f2 = __half22float2(*reinterpret_cast<const __half2*>(&v1.z));
                const float2 f3 = __half22float2(*reinterpret_cast<const __half2*>(&v1.w));
                acc[0] = fmaf(c.x, f0.x, acc[0]); acc[1] = fmaf(c.x, f0.y, acc[1]);
                acc[2] = fmaf(c.x, f1.x, acc[2]); acc[3] = fmaf(c.x, f1.y, acc[3]);
                acc[4] = fmaf(c.x, f2.x, acc[4]); acc[5] = fmaf(c.x, f2.y, acc[5]);
                acc[6] = fmaf(c.x, f3.x, acc[6]); acc[7] = fmaf(c.x, f3.y, acc[7]);
            }
            {
                const float2 f0 = __half22float2(*reinterpret_cast<const __half2*>(&v2.x));
                const float2 f1 = __half22float2(*reinterpret_cast<const __half2*>(&v2.y));
                const float2 f2 = __half22float2(*reinterpret_cast<const __half2*>(&v2.z));
                const float2 f3 = __half22float2(*reinterpret_cast<const __half2*>(&v2.w));
                acc[0] = fmaf(c.y, f0.x, acc[0]); acc[1] = fmaf(c.y, f0.y, acc[1]);
                acc[2] = fmaf(c.y, f1.x, acc[2]); acc[3] = fmaf(c.y, f1.y, acc[3]);
                acc[4] = fmaf(c.y, f2.x, acc[4]); acc[5] = fmaf(c.y, f2.y, acc[5]);
                acc[6] = fmaf(c.y, f3.x, acc[6]); acc[7] = fmaf(c.y, f3.y, acc[7]);
            }
        }

        // cross-half reduction + epilogue (apply 1/Z here)
        if (t >= 128) {
#pragma unroll
            for (int q = 0; q < 8; q++) red[t - 128][q] = acc[q];
        }
        __syncthreads();
        if (t < 128) {
            const float iz = sInvZ[hh_t];
            float4 b0 = *reinterpret_cast<const float4*>(bias + colbase);
            float4 b1 = *reinterpret_cast<const float4*>(bias + colbase + 4);
            float o0 = fmaxf(fmaf(acc[0] + red[t][0], iz, b0.x), 0.0f);
            float o1 = fmaxf(fmaf(acc[1] + red[t][1], iz, b0.y), 0.0f);
            float o2 = fmaxf(fmaf(acc[2] + red[t][2], iz, b0.z), 0.0f);
            float o3 = fmaxf(fmaf(acc[3] + red[t][3], iz, b0.w), 0.0f);
            float o4 = fmaxf(fmaf(acc[4] + red[t][4], iz, b1.x), 0.0f);
            float o5 = fmaxf(fmaf(acc[5] + red[t][5], iz, b1.y), 0.0f);
            float o6 = fmaxf(fmaf(acc[6] + red[t][6], iz, b1.z), 0.0f);
            float o7 = fmaxf(fmaf(acc[7] + red[t][7], iz, b1.w), 0.0f);
            float* dst = out + (size_t)i * HC + colbase;
            *reinterpret_cast<float4*>(dst)     = make_float4(o0, o1, o2, o3);
            *reinterpret_cast<float4*>(dst + 4) = make_float4(o4, o5, o6, o7);
        }
        // loop-top __syncthreads fences smem reuse for the next row
    }
}

// ---------------------------------------------------------------------------
extern "C" void kernel_launch(void* const* d_in, const int* in_sizes, int n_in,
                              void* d_out, int out_size) {
    const float* X       = (const float*)d_in[0];  // [4096, 512]
    const float* A       = (const float*)d_in[1];  // [4096, 4096]
    const float* W       = (const float*)d_in[2];  // [8, 512, 128]
    const float* a_self  = (const float*)d_in[3];  // [8, 128]
    const float* a_neigh = (const float*)d_in[4];  // [8, 128]
    const float* bias    = (const float*)d_in[5];  // [8, 128]
    float* out = (float*)d_out;                    // [4096, 1024]

    cudaFuncSetAttribute(gemm_kernel,
                         cudaFuncAttributeMaxDynamicSharedMemorySize, GEMM_DYN_SMEM);

    prep_kernel<<<2560, 256>>>(X, W);

    // gemm with PDL after prep
    {
        cudaLaunchConfig_t cfg = {};
        cfg.gridDim  = dim3(H_HEADS, N_NODES / 128);
        cfg.blockDim = dim3(256);
        cfg.dynamicSmemBytes = GEMM_DYN_SMEM;
        cfg.stream = 0;
        cudaLaunchAttribute attrs[1];
        attrs[0].id = cudaLaunchAttributeProgrammaticStreamSerialization;
        attrs[0].val.programmaticStreamSerializationAllowed = 1;
        cfg.attrs = attrs;
        cfg.numAttrs = 1;
        cudaError_t e = cudaLaunchKernelEx(&cfg, gemm_kernel, a_self, a_neigh);
        if (e != cudaSuccess)
            gemm_kernel<<<dim3(H_HEADS, N_NODES / 128), 256, GEMM_DYN_SMEM>>>(a_self, a_neigh);
    }

    // agg with PDL after gemm (persistent work-stealing grid)
    {
        cudaLaunchConfig_t cfg = {};
        cfg.gridDim  = dim3(AGG_CTAS);
        cfg.blockDim = dim3(256);
        cfg.dynamicSmemBytes = 0;
        cfg.stream = 0;
        cudaLaunchAttribute attrs[1];
        attrs[0].id = cudaLaunchAttributeProgrammaticStreamSerialization;
        attrs[0].val.programmaticStreamSerializationAllowed = 1;
        cfg.attrs = attrs;
        cfg.numAttrs = 1;
        cudaError_t e = cudaLaunchKernelEx(&cfg, agg_kernel, A, bias, out);
        if (e != cudaSuccess)
            agg_kernel<<<AGG_CTAS, 256>>>(A, bias, out);
    }
}

// round 17
// speedup vs baseline: 1.1023x; 1.1023x over previous
#include <cuda_runtime.h>
#include <cuda_fp16.h>
#include <math.h>

#define N_NODES 4096
#define F_IN 512
#define H_HEADS 8
#define C_OUT 128
#define HC (H_HEADS * C_OUT)   // 1024
#define ALPHA 0.2f
#define MAX_DEG 256   // deg ~ Binom(4096,0.01)+1 = 42±6.4; 256 is a >30-sigma guard

// Scratch (allocation-free rule: __device__ globals)
__device__ __half g_feats_h[N_NODES * HC];    // 8 MB (L2-resident)
__device__ float  g_sself[H_HEADS * N_NODES];
__device__ float  g_sneigh[H_HEADS * N_NODES];
__device__ float  g_Xr[N_NODES * F_IN];          // rna-tf32-rounded X (8 MB)
__device__ float  g_Wr[H_HEADS * F_IN * C_OUT];  // rna-tf32-rounded W (2 MB)

// ---------------------------------------------------------------------------
__device__ __forceinline__ float tf32_rna(float x) {
    unsigned u;
    asm("cvt.rna.tf32.f32 %0, %1;" : "=r"(u) : "f"(x));
    return __uint_as_float(u);
}

__device__ __forceinline__ void mma_tf32(float* c, const unsigned* a, const unsigned* b) {
    asm volatile(
        "mma.sync.aligned.m16n8k8.row.col.f32.tf32.tf32.f32 "
        "{%0,%1,%2,%3}, {%4,%5,%6,%7}, {%8,%9}, {%0,%1,%2,%3};"
        : "+f"(c[0]), "+f"(c[1]), "+f"(c[2]), "+f"(c[3])
        : "r"(a[0]), "r"(a[1]), "r"(a[2]), "r"(a[3]), "r"(b[0]), "r"(b[1]));
}

__device__ __forceinline__ void cp_async16(unsigned smem_addr, const void* gptr) {
    asm volatile("cp.async.cg.shared.global [%0], [%1], 16;"
                 :: "r"(smem_addr), "l"(gptr));
}

// ---------------------------------------------------------------------------
// Prepass: rna-round X and W to tf32. R14's exact measured-best config:
// 2560 blocks x 256 threads, one float4 per thread.
// ---------------------------------------------------------------------------
__global__ __launch_bounds__(256) void prep_kernel(const float* __restrict__ X,
                                                   const float* __restrict__ W) {
    const int idx = blockIdx.x * 256 + threadIdx.x;   // float4 index
    const int nX = N_NODES * F_IN / 4;                // 524288
    const int nW = H_HEADS * F_IN * C_OUT / 4;        // 131072
    if (idx < nX) {
        float4 v = reinterpret_cast<const float4*>(X)[idx];
        v.x = tf32_rna(v.x); v.y = tf32_rna(v.y);
        v.z = tf32_rna(v.z); v.w = tf32_rna(v.w);
        reinterpret_cast<float4*>(g_Xr)[idx] = v;
    } else if (idx < nX + nW) {
        const int j = idx - nX;
        float4 v = reinterpret_cast<const float4*>(W)[j];
        v.x = tf32_rna(v.x); v.y = tf32_rna(v.y);
        v.z = tf32_rna(v.z); v.w = tf32_rna(v.w);
        reinterpret_cast<float4*>(g_Wr)[j] = v;
    }
}

// ---------------------------------------------------------------------------
// TF32 tensor-core GEMM + fused score epilogue. (R14 measured config.)
// Releases the dependent agg grid at entry (PDL).
// ---------------------------------------------------------------------------
#define AS_STRIDE 36   // bank = (4r + c) % 32 -> conflict-free frag loads
#define BS_STRIDE 136  // bank = (8k + n) % 32 -> conflict-free frag loads
#define AS_SIZE (128 * AS_STRIDE)   // floats per buffer
#define BS_SIZE (32 * BS_STRIDE)
#define GEMM_DYN_SMEM ((2 * AS_SIZE + 2 * BS_SIZE) * 4)   // 71680 B

__global__ __launch_bounds__(256, 2) void gemm_kernel(const float* __restrict__ a_self,
                                                      const float* __restrict__ a_neigh) {
    asm volatile("griddepcontrol.launch_dependents;");

    extern __shared__ float dyn[];
    float* Asm = dyn;                  // [2][128][AS_STRIDE]
    float* Bsm = dyn + 2 * AS_SIZE;    // [2][32][BS_STRIDE]
    __shared__ float sredS[4][128];
    __shared__ float sredN[4][128];

    const int h  = blockIdx.x;
    const int m0 = blockIdx.y * 128;
    const float* Xr = g_Xr;
    const float* Wh = g_Wr + (size_t)h * F_IN * C_OUT;

    const int t    = threadIdx.x;
    const int lane = t & 31;
    const int w    = t >> 5;
    const int warp_m = (w & 1) * 64;
    const int warp_n = (w >> 1) * 32;

    float acc[4][4][4];
#pragma unroll
    for (int mt = 0; mt < 4; mt++)
#pragma unroll
        for (int nt = 0; nt < 4; nt++)
#pragma unroll
            for (int q = 0; q < 4; q++) acc[mt][nt][q] = 0.0f;

    const int a_row  = t >> 3;        // 0..31 (+32p)
    const int a_col4 = (t & 7) * 4;
    const int b_row  = t >> 5;        // 0..7 (+8p)
    const int b_col4 = (t & 31) * 4;

    const unsigned sA = (unsigned)__cvta_generic_to_shared(Asm);
    const unsigned sB = (unsigned)__cvta_generic_to_shared(Bsm);

    auto issue_chunk = [&](int chunk) {
        const int buf = chunk & 1;
        const int k0  = chunk * 32;
#pragma unroll
        for (int p = 0; p < 4; p++) {
            cp_async16(sA + (unsigned)(buf * AS_SIZE +
                             (a_row + 32 * p) * AS_STRIDE + a_col4) * 4u,
                       Xr + (size_t)(m0 + a_row + 32 * p) * F_IN + k0 + a_col4);
            cp_async16(sB + (unsigned)(buf * BS_SIZE +
                             (b_row + 8 * p) * BS_STRIDE + b_col4) * 4u,
                       Wh + (size_t)(k0 + b_row + 8 * p) * C_OUT + b_col4);
        }
        asm volatile("cp.async.commit_group;" ::: "memory");
    };

    issue_chunk(0);

    for (int chunk = 0; chunk < F_IN / 32; chunk++) {
        if (chunk + 1 < F_IN / 32) {
            issue_chunk(chunk + 1);
            asm volatile("cp.async.wait_group 1;" ::: "memory");
        } else {
            asm volatile("cp.async.wait_group 0;" ::: "memory");
        }
        __syncthreads();

        const unsigned* Au = reinterpret_cast<const unsigned*>(Asm + (chunk & 1) * AS_SIZE);
        const unsigned* Bu = reinterpret_cast<const unsigned*>(Bsm + (chunk & 1) * BS_SIZE);

#pragma unroll
        for (int ks = 0; ks < 32; ks += 8) {
            unsigned afr[4][4], bfr[4][2];
            const int r0 = warp_m + (lane >> 2);
            const int cA = ks + (lane & 3);
#pragma unroll
            for (int mt = 0; mt < 4; mt++) {
                const int r = r0 + mt * 16;
                afr[mt][0] = Au[r * AS_STRIDE + cA];
                afr[mt][1] = Au[(r + 8) * AS_STRIDE + cA];
                afr[mt][2] = Au[r * AS_STRIDE + cA + 4];
                afr[mt][3] = Au[(r + 8) * AS_STRIDE + cA + 4];
            }
            const int rB = ks + (lane & 3);
            const int nB = warp_n + (lane >> 2);
#pragma unroll
            for (int nt = 0; nt < 4; nt++) {
                bfr[nt][0] = Bu[rB * BS_STRIDE + nB + nt * 8];
                bfr[nt][1] = Bu[(rB + 4) * BS_STRIDE + nB + nt * 8];
            }
#pragma unroll
            for (int mt = 0; mt < 4; mt++)
#pragma unroll
                for (int nt = 0; nt < 4; nt++)
                    mma_tf32(acc[mt][nt], afr[mt], bfr[nt]);
        }
        __syncthreads();
    }

    // ---- Epilogue: fp16 feats store + fused score reduction ----
    const int rloc  = warp_m + (lane >> 2);
    const int cloc  = warp_n + (lane & 3) * 2;
    const int cbase = h * C_OUT + cloc;

    float asf[4][2], anf[4][2];
#pragma unroll
    for (int nt = 0; nt < 4; nt++) {
        float2 s2 = *reinterpret_cast<const float2*>(a_self  + h * C_OUT + cloc + nt * 8);
        float2 n2 = *reinterpret_cast<const float2*>(a_neigh + h * C_OUT + cloc + nt * 8);
        asf[nt][0] = s2.x; asf[nt][1] = s2.y;
        anf[nt][0] = n2.x; anf[nt][1] = n2.y;
    }

#pragma unroll
    for (int mt = 0; mt < 4; mt++) {
#pragma unroll
        for (int p = 0; p < 2; p++) {
            const int r = m0 + rloc + mt * 16 + p * 8;
            float ssp = 0.0f, snp = 0.0f;
#pragma unroll
            for (int nt = 0; nt < 4; nt++) {
                const float v0 = acc[mt][nt][2 * p];
                const float v1 = acc[mt][nt][2 * p + 1];
                ssp = fmaf(v0, asf[nt][0], ssp);
                ssp = fmaf(v1, asf[nt][1], ssp);
                snp = fmaf(v0, anf[nt][0], snp);
                snp = fmaf(v1, anf[nt][1], snp);
                __half2 hv = __floats2half2_rn(v0, v1);
                *reinterpret_cast<__half2*>(g_feats_h + (size_t)r * HC + cbase + nt * 8) = hv;
            }
            ssp += __shfl_xor_sync(0xffffffffu, ssp, 1);
            ssp += __shfl_xor_sync(0xffffffffu, ssp, 2);
            snp += __shfl_xor_sync(0xffffffffu, snp, 1);
            snp += __shfl_xor_sync(0xffffffffu, snp, 2);
            if ((lane & 3) == 0) {
                const int rl = rloc + mt * 16 + p * 8;
                sredS[w >> 1][rl] = ssp;
                sredN[w >> 1][rl] = snp;
            }
        }
    }
    __syncthreads();
    if (t < 128) {
        float ss = sredS[0][t] + sredS[1][t] + sredS[2][t] + sredS[3][t];
        float sn = sredN[0][t] + sredN[1][t] + sredN[2][t] + sredN[3][t];
        g_sself[h * N_NODES + m0 + t]  = ss;
        g_sneigh[h * N_NODES + m0 + t] = sn;
    }
}

// ---------------------------------------------------------------------------
// Aggregation: one CTA per row i (R15's measured config). Phase 1 reads only
// A (overlaps gemm tail under PDL); griddepcontrol.wait before phase 2.
// ---------------------------------------------------------------------------
__global__ __launch_bounds__(256) void agg_kernel(const float* __restrict__ A,
                                                  const float* __restrict__ bias,
                                                  float* __restrict__ out) {
    __shared__ int   nbr[MAX_DEG];             // 1 KB
    __shared__ float exps_t[H_HEADS][MAX_DEG]; // 8 KB (unnormalized e)
    __shared__ int   warp_cnt[8];
    __shared__ float sInvZ[H_HEADS];
    __shared__ float red[128][8];              // 4 KB

    const int i    = blockIdx.x;
    const int t    = threadIdx.x;
    const int lane = t & 31;
    const int w    = t >> 5;

    const float* Arow = A + (size_t)i * N_NODES;

    // ---- 1) compaction: count first, then write at final position ----
    float4 v4[4];
    unsigned bal[16];
    {
        const float* Aseg = Arow + (w << 9);  // warp owns 512 cols
#pragma unroll
        for (int b = 0; b < 4; b++)
            v4[b] = reinterpret_cast<const float4*>(Aseg)[(b << 5) + lane];  // MLP=4x16B
        int wcnt = 0;
        const float* vf = reinterpret_cast<const float*>(v4);
#pragma unroll
        for (int s = 0; s < 16; s++) {
            const bool p = (vf[s] != 0.0f);
            bal[s] = __ballot_sync(0xffffffffu, p);
            wcnt += __popc(bal[s]);
        }
        if (lane == 0) warp_cnt[w] = wcnt;
    }
    __syncthreads();

    int pref[9];
    pref[0] = 0;
#pragma unroll
    for (int ww = 0; ww < 8; ww++) pref[ww + 1] = pref[ww] + warp_cnt[ww];
    const int deg  = min(pref[8], MAX_DEG);          // >= 1 (self loop)
    const int degp = min((deg + 3) & ~3, MAX_DEG);   // padded to mult of 4

    {
        const unsigned lmask = (1u << lane) - 1u;
        int running = pref[w];
        const float* vf = reinterpret_cast<const float*>(v4);
#pragma unroll
        for (int s = 0; s < 16; s++) {
            const bool p = (vf[s] != 0.0f);
            if (p) {
                const int pos = running + __popc(bal[s] & lmask);
                const int col = (w << 9) + ((s >> 2) << 7) + (lane << 2) + (s & 3);
                if (pos < MAX_DEG) nbr[pos] = col;
            }
            running += __popc(bal[s]);
        }
        if (t < 4 && deg + t < degp) nbr[deg + t] = 0;
    }
    __syncthreads();

    // PDL join: gemm's stores visible after this (no-op on plain launch).
    asm volatile("griddepcontrol.wait;" ::: "memory");

    // ---- 2) exp pass + Z; warp w handles head w (no max shift) ----
    {
        const float ss = g_sself[(w << 12) + i];
        const float* snh = g_sneigh + (w << 12);
        float Z = 0.0f;
        for (int k = lane; k < degp; k += 32) {
            float e = 0.0f;
            if (k < deg) {
                float x = ss + snh[nbr[k]];
                x = (x > 0.0f) ? x : ALPHA * x;
                e = __expf(x);
            }
            exps_t[w][k] = e;
            Z += e;
        }
#pragma unroll
        for (int o = 16; o > 0; o >>= 1)
            Z += __shfl_xor_sync(0xffffffffu, Z, o);
        if (lane == 0) sInvZ[w] = 1.0f / Z;
    }
    __syncthreads();

    // ---- 3) sync-free gather: adjacent pair per thread, LDS.64 coefs ----
    const int hh_t    = (t & 127) >> 4;
    const unsigned colbase = (unsigned)((t & 127) << 3);
    const int ksel    = t >> 7;
    float acc[8];
#pragma unroll
    for (int q = 0; q < 8; q++) acc[q] = 0.0f;

    for (int m = 0; m < degp; m += 4) {
        const int k1 = m + (ksel << 1);
        const int j1 = nbr[k1];
        const int j2 = nbr[k1 + 1];
        const uint4 v1 = *reinterpret_cast<const uint4*>(
            g_feats_h + (((unsigned)j1) << 10) + colbase);
        const uint4 v2 = *reinterpret_cast<const uint4*>(
            g_feats_h + (((unsigned)j2) << 10) + colbase);
        const float2 c = *reinterpret_cast<const float2*>(&exps_t[hh_t][k1]);
        {
            const float2 f0 = __half22float2(*reinterpret_cast<const __half2*>(&v1.x));
            const float2 f1 = __half22float2(*reinterpret_cast<const __half2*>(&v1.y));
            const float2 f2 = __half22float2(*reinterpret_cast<const __half2*>(&v1.z));
            const float2 f3 = __half22float2(*reinterpret_cast<const __half2*>(&v1.w));
            acc[0] = fmaf(c.x, f0.x, acc[0]); acc[1] = fmaf(c.x, f0.y, acc[1]);
            acc[2] = fmaf(c.x, f1.x, acc[2]); acc[3] = fmaf(c.x, f1.y, acc[3]);
            acc[4] = fmaf(c.x, f2.x, acc[4]); acc[5] = fmaf(c.x, f2.y, acc[5]);
            acc[6] = fmaf(c.x, f3.x, acc[6]); acc[7] = fmaf(c.x, f3.y, acc[7]);
        }
        {
            const float2 f0 = __half22float2(*reinterpret_cast<const __half2*>(&v2.x));
            const float2 f1 = __half22float2(*reinterpret_cast<const __half2*>(&v2.y));
            const float2 f2 = __half22float2(*reinterpret_cast<const __half2*>(&v2.z));
            const float2 f3 = __half22float2(*reinterpret_cast<const __half2*>(&v2.w));
            acc[0] = fmaf(c.y, f0.x, acc[0]); acc[1] = fmaf(c.y, f0.y, acc[1]);
            acc[2] = fmaf(c.y, f1.x, acc[2]); acc[3] = fmaf(c.y, f1.y, acc[3]);
            acc[4] = fmaf(c.y, f2.x, acc[4]); acc[5] = fmaf(c.y, f2.y, acc[5]);
            acc[6] = fmaf(c.y, f3.x, acc[6]); acc[7] = fmaf(c.y, f3.y, acc[7]);
        }
    }

    // cross-half reduction + epilogue (apply 1/Z here)
    if (t >= 128) {
#pragma unroll
        for (int q = 0; q < 8; q++) red[t - 128][q] = acc[q];
    }
    __syncthreads();
    if (t < 128) {
        const float iz = sInvZ[hh_t];
        float4 b0 = *reinterpret_cast<const float4*>(bias + colbase);
        float4 b1 = *reinterpret_cast<const float4*>(bias + colbase + 4);
        float o0 = fmaxf(fmaf(acc[0] + red[t][0], iz, b0.x), 0.0f);
        float o1 = fmaxf(fmaf(acc[1] + red[t][1], iz, b0.y), 0.0f);
        float o2 = fmaxf(fmaf(acc[2] + red[t][2], iz, b0.z), 0.0f);
        float o3 = fmaxf(fmaf(acc[3] + red[t][3], iz, b0.w), 0.0f);
        float o4 = fmaxf(fmaf(acc[4] + red[t][4], iz, b1.x), 0.0f);
        float o5 = fmaxf(fmaf(acc[5] + red[t][5], iz, b1.y), 0.0f);
        float o6 = fmaxf(fmaf(acc[6] + red[t][6], iz, b1.z), 0.0f);
        float o7 = fmaxf(fmaf(acc[7] + red[t][7], iz, b1.w), 0.0f);
        float* dst = out + (size_t)i * HC + colbase;
        *reinterpret_cast<float4*>(dst)     = make_float4(o0, o1, o2, o3);
        *reinterpret_cast<float4*>(dst + 4) = make_float4(o4, o5, o6, o7);
    }
}

// ---------------------------------------------------------------------------
extern "C" void kernel_launch(void* const* d_in, const int* in_sizes, int n_in,
                              void* d_out, int out_size) {
    const float* X       = (const float*)d_in[0];  // [4096, 512]
    const float* A       = (const float*)d_in[1];  // [4096, 4096]
    const float* W       = (const float*)d_in[2];  // [8, 512, 128]
    const float* a_self  = (const float*)d_in[3];  // [8, 128]
    const float* a_neigh = (const float*)d_in[4];  // [8, 128]
    const float* bias    = (const float*)d_in[5];  // [8, 128]
    float* out = (float*)d_out;                    // [4096, 1024]

    cudaFuncSetAttribute(gemm_kernel,
                         cudaFuncAttributeMaxDynamicSharedMemorySize, GEMM_DYN_SMEM);

    prep_kernel<<<2560, 256>>>(X, W);
    gemm_kernel<<<dim3(H_HEADS, N_NODES / 128), 256, GEMM_DYN_SMEM>>>(a_self, a_neigh);

    // agg with Programmatic Dependent Launch (measured win in R15):
    // compaction (A only) overlaps the gemm tail; griddepcontrol.wait orders
    // the gemm-dependent phases.
    cudaLaunchConfig_t cfg = {};
    cfg.gridDim  = dim3(N_NODES);
    cfg.blockDim = dim3(256);
    cfg.dynamicSmemBytes = 0;
    cfg.stream = 0;
    cudaLaunchAttribute attrs[1];
    attrs[0].id = cudaLaunchAttributeProgrammaticStreamSerialization;
    attrs[0].val.programmaticStreamSerializationAllowed = 1;
    cfg.attrs = attrs;
    cfg.numAttrs = 1;
    cudaError_t e = cudaLaunchKernelEx(&cfg, agg_kernel, A, bias, out);
    if (e != cudaSuccess) {
        agg_kernel<<<N_NODES, 256>>>(A, bias, out);
    }
}